// round 14
// baseline (speedup 1.0000x reference)
#include <cuda_runtime.h>
#include <stdint.h>

// Problem constants
#define BINSD   512
#define BATCH   64
#define NPTS    4096
#define CELLS   (BATCH * BINSD * BINSD)      // 16,777,216 cells
#define FILL_BLOCKS 65536                    // 1 float4 store/thread (R1 shape)

// smem hash: 8192 slots x uint32 = 32 KB. entry = (cell18 << 13) | tok13,
// tok in 1..4096 (occupied entries are nonzero).
#define HASH_SLOTS 8192
#define HASH_MASK  (HASH_SLOTS - 1)

// Slot-indexed winner list: one 16B record per hash slot, rewritten in full
// every replay (valid: .z bits != 0; .z carries cell+1 as raw bits).
static __device__ float4 g_wlist[BATCH * HASH_SLOTS];   // 8 MB scratch

// ---------------------------------------------------------------------------
// Fill: R1-exact shape (one float4 store/thread, huge grid, ZERO smem —
// R12 showed static smem in this kernel starves L1 and 2.5x's the stream).
// ---------------------------------------------------------------------------
__global__ void __launch_bounds__(256) fill_kernel(float4* __restrict__ out) {
    int idx = blockIdx.x * 256 + threadIdx.x;          // 0 .. CELLS-1
    const float inv = 1.0f / (float)BINSD;
    int j = idx & (BINSD - 1);
    int i = (idx >> 9) & (BINSD - 1);
    out[idx] = make_float4(0.63f, 0.63f, (float)j * inv, (float)i * inv);
}

// ---------------------------------------------------------------------------
// Hash dedup: one block per batch; exact last-write-wins via max-token in a
// shared open-addressing hash. Readout dumps ALL slots (coalesced, zeros
// included) into the slot-indexed global list — no compaction counter, no
// smem atomicAdd contention. Never touches `out`: race-free alongside fill.
// ---------------------------------------------------------------------------
__global__ void __launch_bounds__(1024) hash_kernel(
    const float4* __restrict__ pts4) {
    __shared__ unsigned int h[HASH_SLOTS];

    int b   = blockIdx.x;
    int tid = threadIdx.x;

    #pragma unroll
    for (int s = 0; s < 8; s++) h[tid + s * 1024] = 0u;
    __syncthreads();

    // insert: 4 points per thread (two coalesced float4 loads)
    const float4* base4 = pts4 + ((size_t)b << 11);    // 4096 pts = 2048 f4
    int t0 = tid * 4;
    float4 A = base4[tid * 2];
    float4 B = base4[tid * 2 + 1];
    float px[4] = {A.x, A.z, B.x, B.z};
    float py[4] = {A.y, A.w, B.y, B.w};

    #pragma unroll
    for (int k = 0; k < 4; k++) {
        // delta = 1/512 exactly: x/delta == x*512.0f bit-exactly; truncation
        // matches astype(int32) for non-negative inputs.
        int row = (int)(px[k] * 512.0f);
        int col = (int)(py[k] * 512.0f);
        unsigned int cell = (unsigned int)((row << 9) | col);   // 18 bits
        unsigned int ent  = (cell << 13) | (unsigned int)(t0 + k + 1);
        unsigned int slot = cell & HASH_MASK;
        // CAS-claim empty slot, or atomicMax on own key (equal key bits ->
        // max == max token == last write in reference order).
        for (;;) {
            unsigned int cur = h[slot];
            if (cur == 0u) {
                unsigned int prev = atomicCAS(&h[slot], 0u, ent);
                if (prev == 0u) break;
                cur = prev;
            }
            if ((cur >> 13) == cell) { atomicMax(&h[slot], ent); break; }
            slot = (slot + 1) & HASH_MASK;
        }
    }
    __syncthreads();

    // readout: dump all slots, coalesced. Valid entries carry {x, y, cell+1
    // as raw bits}; empty slots write zeros. (Raw bits round-trip exactly —
    // no FP arithmetic ever touches .z.)
    const float2* base2 = (const float2*)base4;
    float4* dst = g_wlist + ((size_t)b << 13);
    #pragma unroll
    for (int s = 0; s < 8; s++) {
        int slot = tid + s * 1024;
        unsigned int ent = h[slot];
        float4 rec = make_float4(0.0f, 0.0f, 0.0f, 0.0f);
        if (ent != 0u) {
            unsigned int cell = ent >> 13;
            unsigned int tok  = ent & 0x1FFFu;
            float2 wp = base2[tok - 1u];               // L1/L2-hot reload
            rec = make_float4(wp.x, wp.y, __uint_as_float(cell + 1u), 0.0f);
        }
        dst[slot] = rec;
    }
}

// ---------------------------------------------------------------------------
// Writeback: flat pass over all 512K slot records. One coalesced 16B read,
// predicate on .z bits, one scattered 16B store. No count, no second load.
// ---------------------------------------------------------------------------
__global__ void __launch_bounds__(256) writeback_kernel(
    float4* __restrict__ out) {
    int idx = blockIdx.x * 256 + threadIdx.x;          // 0 .. BATCH*8192-1
    float4 e = g_wlist[idx];
    unsigned int zbits = __float_as_uint(e.z);
    if (zbits != 0u) {
        int b = idx >> 13;
        unsigned int cell = zbits - 1u;
        out[((size_t)b << 18) + cell] = make_float4(1.0f, 1.0f, e.x, e.y);
    }
}

// Host-side stream/event for the parallel branch (host resources only).
static cudaStream_t g_hstream = nullptr;
static cudaEvent_t  g_fork = nullptr, g_join = nullptr;

extern "C" void kernel_launch(void* const* d_in, const int* in_sizes, int n_in,
                              void* d_out, int out_size) {
    const float4* pts4 = (const float4*)d_in[0];  // batch [64, 4096, 2] fp32
    float4* out = (float4*)d_out;                 // [64, 512, 512, 4] fp32

    if (g_hstream == nullptr) {
        cudaStreamCreateWithFlags(&g_hstream, cudaStreamNonBlocking);
        cudaEventCreateWithFlags(&g_fork, cudaEventDisableTiming);
        cudaEventCreateWithFlags(&g_join, cudaEventDisableTiming);
    }

    // Fork: hash on g_hstream runs concurrently with fill on the main stream.
    cudaEventRecord(g_fork, 0);
    cudaStreamWaitEvent(g_hstream, g_fork, 0);
    hash_kernel<<<BATCH, 1024, 0, g_hstream>>>(pts4);
    fill_kernel<<<FILL_BLOCKS, 256>>>(out);
    // Join: writeback needs both branches complete.
    cudaEventRecord(g_join, g_hstream);
    cudaStreamWaitEvent(0, g_join, 0);
    writeback_kernel<<<(BATCH * HASH_SLOTS) / 256, 256>>>(out);
}